// round 3
// baseline (speedup 1.0000x reference)
#include <cuda_runtime.h>

// ---------------------------------------------------------------------------
// Problem constants
// ---------------------------------------------------------------------------
#define EPSF 1e-8f

constexpr int NQ = 8192;     // queries
constexpr int NK = 524288;   // keys
constexpr int D  = 128;      // head_dim
constexpr int NF = 64;       // num_freqs
constexpr int NB = 128;      // num_bins
constexpr int DT = 192;      // D + NF  (GEMM K-dimension: K values ++ K magnitudes)

// ---------------------------------------------------------------------------
// Device scratch (no allocations allowed)
// ---------------------------------------------------------------------------
__device__ float  g_W[DT * NB];      // W[k][b]: k<128 -> rotated_probes[b][k]; k>=128 -> kmw[b][k-128]
__device__ float2 g_rpq[NF * NB];    // rotated probe pairs, [f][b]
__device__ float  g_effw[NF * NB];   // -softplus(q_weights_raw), [f][b]
__device__ float  g_qmw[NF * NB];    // q_magnitude_weights, [f][b]

// ---------------------------------------------------------------------------
// Helpers
// ---------------------------------------------------------------------------
typedef unsigned long long ull;

__device__ __forceinline__ float sqrt_approx(float x) {
    float y;
    asm("sqrt.approx.f32 %0, %1;" : "=f"(y) : "f"(x));
    return y;
}

__device__ __forceinline__ ull pack2(float lo, float hi) {
    ull r;
    asm("mov.b64 %0, {%1, %2};" : "=l"(r) : "f"(lo), "f"(hi));
    return r;
}

__device__ __forceinline__ float2 unpack2(ull v) {
    float2 r;
    asm("mov.b64 {%0, %1}, %2;" : "=f"(r.x), "=f"(r.y) : "l"(v));
    return r;
}

// packed dual-FMA: d.lo += a.lo*b.lo ; d.hi += a.hi*b.hi   (Blackwell f32x2 pipe)
__device__ __forceinline__ void ffma2(ull& d, ull a, ull b) {
    asm("fma.rn.f32x2 %0, %1, %2, %0;" : "+l"(d) : "l"(a), "l"(b));
}

// ---------------------------------------------------------------------------
// Prep kernel: rotated probes + transposed weight tables (1 block, 128 thr)
// ---------------------------------------------------------------------------
__global__ void prep_kernel(const float* __restrict__ angles,
                            const float* __restrict__ probes,
                            const float* __restrict__ kmw,
                            const float* __restrict__ qraw,
                            const float* __restrict__ qmw)
{
    __shared__ float sc[NF], ss[NF];
    const int b = threadIdx.x;  // 0..127 = bin
    if (b < NF) {
        float a = angles[b];
        sc[b] = cosf(a);
        ss[b] = sinf(a);
    }
    __syncthreads();

    float sum = 0.0f;
    #pragma unroll 4
    for (int d = 0; d < D; d++) {
        float v = probes[b * D + d];
        sum = fmaf(v, v, sum);
    }
    float inv = 1.0f / (sqrtf(sum) + EPSF);

    for (int f = 0; f < NF; f++) {
        float p0 = probes[b * D + 2 * f]     * inv;
        float p1 = probes[b * D + 2 * f + 1] * inv;
        float r0 = p0 * sc[f] - p1 * ss[f];
        float r1 = p0 * ss[f] + p1 * sc[f];
        g_W[(2 * f)     * NB + b] = r0;
        g_W[(2 * f + 1) * NB + b] = r1;
        g_rpq[f * NB + b] = make_float2(r0, r1);
        g_W[(D + f) * NB + b] = kmw[b * NF + f];

        float x  = qraw[b * NF + f];
        float sp = fmaxf(x, 0.0f) + log1pf(expf(-fabsf(x)));
        g_effw[f * NB + b] = -sp;
        g_qmw[f * NB + b]  = qmw[b * NF + f];
    }
}

// ---------------------------------------------------------------------------
// K path: k_logits[r][b] = sum_k A[r][k] * W[k][b] + k_bias[b]
//   A[r][0..127]   = K[r][:]
//   A[r][128..191] = sqrt(K[r][2f]^2 + K[r][2f+1]^2 + eps)
// Tiled GEMM, weights resident in smem, packed f32x2 FMA (bins paired).
// ---------------------------------------------------------------------------
constexpr int TILE_M          = 128;
constexpr int KTHREADS        = 256;
constexpr int TILES_PER_BLOCK = 4;
constexpr int SA_STRIDE       = 193;   // odd stride -> conflict-free row access

__global__ void __launch_bounds__(KTHREADS, 1)
kpath_kernel(const float* __restrict__ Kmat,
             const float* __restrict__ kbias,
             float* __restrict__ out)
{
    extern __shared__ float smem[];
    float* sW = smem;                       // DT*NB          = 24576 floats
    float* sA = sW + DT * NB;               // TILE_M*193     = 24704 floats
    float* sB = sA + TILE_M * SA_STRIDE;    // NB             = 128 floats

    const int tid = threadIdx.x;
    const int tx  = tid & 7;    // bin-pair lane: bins b = i*16 + tx*2, i=0..7
    const int ty  = tid >> 3;   // 0..31 -> rows ty*4 .. ty*4+3

    // Load weight matrix + bias once per block
    for (int i = tid; i < DT * NB; i += KTHREADS) sW[i] = g_W[i];
    if (tid < NB) sB[tid] = kbias[tid];

    const int r0off = (ty * 4 + 0) * SA_STRIDE;
    const int r1off = (ty * 4 + 1) * SA_STRIDE;
    const int r2off = (ty * 4 + 2) * SA_STRIDE;
    const int r3off = (ty * 4 + 3) * SA_STRIDE;
    const ull* wbase = reinterpret_cast<const ull*>(sW) + tx;  // ull idx = k*64 + i*8 + tx

    for (int t = 0; t < TILES_PER_BLOCK; t++) {
        const int rowBase = (blockIdx.x * TILES_PER_BLOCK + t) * TILE_M;
        __syncthreads();  // sW/sB ready on first iter; sA free of readers on later iters

        // Stage K tile (float4, fully coalesced)
        const float4* K4 = reinterpret_cast<const float4*>(Kmat) + (size_t)rowBase * (D / 4);
        for (int i = tid; i < TILE_M * (D / 4); i += KTHREADS) {
            int row = i >> 5, c4 = i & 31;
            float4 v = K4[row * (D / 4) + c4];
            float* dst = sA + row * SA_STRIDE + c4 * 4;
            dst[0] = v.x; dst[1] = v.y; dst[2] = v.z; dst[3] = v.w;
        }
        __syncthreads();

        // Magnitude columns
        for (int i = tid; i < TILE_M * NF; i += KTHREADS) {
            int row = i >> 6, f = i & 63;
            float a0 = sA[row * SA_STRIDE + 2 * f];
            float a1 = sA[row * SA_STRIDE + 2 * f + 1];
            sA[row * SA_STRIDE + D + f] = sqrt_approx(fmaf(a0, a0, fmaf(a1, a1, EPSF)));
        }
        __syncthreads();

        // GEMM: 4 rows x 16 bins per thread, bins packed as f32x2 pairs
        ull acc[4][8];
        #pragma unroll
        for (int r = 0; r < 4; r++)
            #pragma unroll
            for (int i = 0; i < 8; i++) acc[r][i] = 0ull;

        #pragma unroll 2
        for (int k = 0; k < DT; k++) {
            float a0 = sA[r0off + k];
            float a1 = sA[r1off + k];
            float a2 = sA[r2off + k];
            float a3 = sA[r3off + k];
            ull ap0 = pack2(a0, a0);
            ull ap1 = pack2(a1, a1);
            ull ap2 = pack2(a2, a2);
            ull ap3 = pack2(a3, a3);
            const ull* w = wbase + k * 64;
            #pragma unroll
            for (int i = 0; i < 8; i++) {
                ull wp = w[i * 8];
                ffma2(acc[0][i], ap0, wp);
                ffma2(acc[1][i], ap1, wp);
                ffma2(acc[2][i], ap2, wp);
                ffma2(acc[3][i], ap3, wp);
            }
        }

        // Epilogue: bias + store
        #pragma unroll
        for (int r = 0; r < 4; r++) {
            const int grow = rowBase + ty * 4 + r;
            float* orow = out + (size_t)grow * NB;
            #pragma unroll
            for (int i = 0; i < 8; i++) {
                float2 v = unpack2(acc[r][i]);
                int b0 = i * 16 + tx * 2;
                v.x += sB[b0];
                v.y += sB[b0 + 1];
                *reinterpret_cast<float2*>(orow + b0) = v;
            }
        }
    }
}

// ---------------------------------------------------------------------------
// Q path: q_logits[q][b] = sum_f |rp[b][f] - Qn[q][f]| * effw[b][f]
//                        + sum_f Qmag[q][f] * qmw[b][f] + q_bias[b]
// 32 queries per block, all tables resident in smem.
// ---------------------------------------------------------------------------
constexpr int QTHREADS = 256;
constexpr int QPB      = 32;

__global__ void __launch_bounds__(QTHREADS, 1)
qpath_kernel(const float* __restrict__ Q,
             const float* __restrict__ qbias,
             float* __restrict__ outq)
{
    extern __shared__ float smem[];
    float2* sRP  = reinterpret_cast<float2*>(smem);      // NF*NB float2
    float* sEW   = smem + 2 * NF * NB;                   // NF*NB
    float* sMW   = sEW + NF * NB;                        // NF*NB
    float* sQn   = sMW + NF * NB;                        // QPB*D
    float* sQmag = sQn + QPB * D;                        // QPB*NF
    float* sInv  = sQmag + QPB * NF;                     // QPB
    float* sQB   = sInv + QPB;                           // NB

    const int tid = threadIdx.x;
    for (int i = tid; i < NF * NB; i += QTHREADS) {
        sRP[i] = g_rpq[i];
        sEW[i] = g_effw[i];
        sMW[i] = g_qmw[i];
    }
    if (tid < NB) sQB[tid] = qbias[tid];

    const int qbase = blockIdx.x * QPB;
    for (int i = tid; i < QPB * D; i += QTHREADS)
        sQn[i] = Q[(size_t)qbase * D + i];
    __syncthreads();

    // L2 norms: 8 threads per query
    {
        int q = tid >> 3, l8 = tid & 7;
        float s = 0.0f;
        #pragma unroll
        for (int j = 0; j < D / 8; j++) {
            float v = sQn[q * D + l8 + 8 * j];
            s = fmaf(v, v, s);
        }
        s += __shfl_down_sync(0xffffffffu, s, 4, 8);
        s += __shfl_down_sync(0xffffffffu, s, 2, 8);
        s += __shfl_down_sync(0xffffffffu, s, 1, 8);
        if (l8 == 0) sInv[q] = 1.0f / (sqrtf(s) + EPSF);
    }
    __syncthreads();
    for (int i = tid; i < QPB * D; i += QTHREADS)
        sQn[i] *= sInv[i >> 7];
    __syncthreads();
    for (int i = tid; i < QPB * NF; i += QTHREADS) {
        int q = i >> 6, f = i & 63;
        float a = sQn[q * D + 2 * f];
        float c = sQn[q * D + 2 * f + 1];
        sQmag[i] = sqrt_approx(fmaf(a, a, fmaf(c, c, EPSF)));
    }
    __syncthreads();

    const int b  = tid & 127;
    const int qg = tid >> 7;    // 0/1: 16 queries each
    float acc[16];
    #pragma unroll
    for (int j = 0; j < 16; j++) acc[j] = 0.0f;

    for (int f = 0; f < NF; f++) {
        float2 rp = sRP[f * NB + b];
        float  ew = sEW[f * NB + b];
        float  mw = sMW[f * NB + b];
        #pragma unroll
        for (int j = 0; j < 16; j++) {
            int q = qg * 16 + j;
            float2 qp = *reinterpret_cast<const float2*>(sQn + q * D + 2 * f);
            float d0 = rp.x - qp.x;
            float d1 = rp.y - qp.y;
            float dist = sqrt_approx(fmaf(d0, d0, fmaf(d1, d1, EPSF)));
            acc[j] = fmaf(dist, ew, acc[j]);
            acc[j] = fmaf(sQmag[q * NF + f], mw, acc[j]);
        }
    }

    #pragma unroll
    for (int j = 0; j < 16; j++) {
        int q = qbase + qg * 16 + j;
        outq[(size_t)q * NB + b] = acc[j] + sQB[b];
    }
}

// ---------------------------------------------------------------------------
// Launch
// ---------------------------------------------------------------------------
extern "C" void kernel_launch(void* const* d_in, const int* in_sizes, int n_in,
                              void* d_out, int out_size)
{
    const float* Q      = (const float*)d_in[0];
    const float* Kmat   = (const float*)d_in[1];
    const float* angles = (const float*)d_in[2];
    const float* probes = (const float*)d_in[3];
    const float* kmw    = (const float*)d_in[4];
    const float* kbias  = (const float*)d_in[5];
    const float* qraw   = (const float*)d_in[6];
    const float* qmw    = (const float*)d_in[7];
    const float* qbias  = (const float*)d_in[8];
    float* out = (float*)d_out;

    const size_t smemK = (size_t)(DT * NB + TILE_M * SA_STRIDE + NB) * sizeof(float);   // 197,632 B
    const size_t smemQ = (size_t)(2 * NF * NB + NF * NB + NF * NB + QPB * D + QPB * NF
                                  + QPB + NB) * sizeof(float);                          // 156,288 B

    cudaFuncSetAttribute(kpath_kernel, cudaFuncAttributeMaxDynamicSharedMemorySize, (int)smemK);
    cudaFuncSetAttribute(qpath_kernel, cudaFuncAttributeMaxDynamicSharedMemorySize, (int)smemQ);

    prep_kernel<<<1, 128>>>(angles, probes, kmw, qraw, qmw);
    kpath_kernel<<<NK / (TILE_M * TILES_PER_BLOCK), KTHREADS, smemK>>>(Kmat, kbias, out);
    qpath_kernel<<<NQ / QPB, QTHREADS, smemQ>>>(Q, qbias, out + (size_t)NK * NB);
}

// round 5
// speedup vs baseline: 2.1017x; 2.1017x over previous
#include <cuda_runtime.h>
#include <cuda_bf16.h>
#include <cstdint>

// ---------------------------------------------------------------------------
// Problem constants
// ---------------------------------------------------------------------------
#define EPSF 1e-8f

constexpr int NQ = 8192;     // queries
constexpr int NK = 524288;   // keys
constexpr int D  = 128;      // head_dim
constexpr int NF = 64;       // num_freqs
constexpr int NB = 128;      // num_bins
constexpr int DT = 192;      // D + NF  (GEMM K-dimension)

constexpr int STRIDE = 200;              // bf16 elems per row (padded; 400B -> conflict-free ldmatrix)
constexpr int WBUF_BYTES = 128 * STRIDE * 2;   // 51,200 B per hi/lo buffer

// ---------------------------------------------------------------------------
// Device scratch (no allocations allowed)
// ---------------------------------------------------------------------------
// W hi/lo in final smem layout: [bin][k], stride 200 bf16
__device__ __align__(16) __nv_bfloat16 g_Whi[128 * STRIDE];
__device__ __align__(16) __nv_bfloat16 g_Wlo[128 * STRIDE];
__device__ float2 g_rpq[NF * NB];    // rotated probe pairs, [f][b]
__device__ float  g_effw[NF * NB];   // -softplus(q_weights_raw), [f][b]
__device__ float  g_qmw[NF * NB];    // q_magnitude_weights, [f][b]

// ---------------------------------------------------------------------------
// Helpers
// ---------------------------------------------------------------------------
__device__ __forceinline__ float sqrt_approx(float x) {
    float y;
    asm("sqrt.approx.f32 %0, %1;" : "=f"(y) : "f"(x));
    return y;
}

// bf16 hi/lo split: x ~= hi + lo  (error ~2^-17 relative)
__device__ __forceinline__ void bsplit(float x, __nv_bfloat16& h, __nv_bfloat16& l) {
    h = __float2bfloat16_rn(x);
    l = __float2bfloat16_rn(x - __bfloat162float(h));
}

__device__ __forceinline__ void st_bf2(char* base, int eidx, __nv_bfloat16 a, __nv_bfloat16 b) {
    *reinterpret_cast<__nv_bfloat162*>(base + 2 * eidx) = __halves2bfloat162(a, b);
}

__device__ __forceinline__ uint32_t smem_u32(const void* p) {
    uint32_t a;
    asm("{ .reg .u64 t; cvta.to.shared.u64 t, %1; cvt.u32.u64 %0, t; }" : "=r"(a) : "l"(p));
    return a;
}

__device__ __forceinline__ void ldm4(uint32_t* r, uint32_t addr) {
    asm volatile("ldmatrix.sync.aligned.m8n8.x4.shared.b16 {%0,%1,%2,%3}, [%4];"
        : "=r"(r[0]), "=r"(r[1]), "=r"(r[2]), "=r"(r[3]) : "r"(addr));
}

__device__ __forceinline__ void mma16816(float* c, const uint32_t* a, const uint32_t* b) {
    asm volatile("mma.sync.aligned.m16n8k16.row.col.f32.bf16.bf16.f32 "
        "{%0,%1,%2,%3}, {%4,%5,%6,%7}, {%8,%9}, {%0,%1,%2,%3};"
        : "+f"(c[0]), "+f"(c[1]), "+f"(c[2]), "+f"(c[3])
        : "r"(a[0]), "r"(a[1]), "r"(a[2]), "r"(a[3]), "r"(b[0]), "r"(b[1]));
}

// ---------------------------------------------------------------------------
// Prep kernel: one block per bin, 64 threads (one per freq)
// ---------------------------------------------------------------------------
__global__ void prep_kernel(const float* __restrict__ angles,
                            const float* __restrict__ probes,
                            const float* __restrict__ kmw,
                            const float* __restrict__ qraw,
                            const float* __restrict__ qmw)
{
    __shared__ float red[2];
    const int b = blockIdx.x;
    const int f = threadIdx.x;   // 0..63

    float p0 = probes[b * D + 2 * f];
    float p1 = probes[b * D + 2 * f + 1];
    float s = fmaf(p0, p0, p1 * p1);
    #pragma unroll
    for (int o = 16; o; o >>= 1) s += __shfl_xor_sync(0xffffffffu, s, o);
    if ((f & 31) == 0) red[f >> 5] = s;
    __syncthreads();
    float inv = 1.0f / (sqrtf(red[0] + red[1]) + EPSF);
    p0 *= inv; p1 *= inv;

    float a  = angles[f];
    float ca = cosf(a), sa = sinf(a);
    float r0 = p0 * ca - p1 * sa;
    float r1 = p0 * sa + p1 * ca;
    g_rpq[f * NB + b] = make_float2(r0, r1);

    // W[bin][k] stride 200: k = 2f, 2f+1 <- rotated probe pair
    __nv_bfloat16 h0, l0, h1, l1;
    bsplit(r0, h0, l0); bsplit(r1, h1, l1);
    int e = b * STRIDE + 2 * f;
    st_bf2((char*)g_Whi, e, h0, h1);
    st_bf2((char*)g_Wlo, e, l0, l1);

    // k = 128+f <- k_magnitude_weights[b][f]
    float w = kmw[b * NF + f];
    __nv_bfloat16 wh, wl;
    bsplit(w, wh, wl);
    int em = b * STRIDE + D + f;
    g_Whi[em] = wh;
    g_Wlo[em] = wl;

    // zero the pad columns so nothing is garbage (never read, but be safe)
    if (f < 8) { g_Whi[b * STRIDE + 192 + f] = __float2bfloat16(0.f); g_Wlo[b * STRIDE + 192 + f] = __float2bfloat16(0.f); }

    // Q-path tables
    float x  = qraw[b * NF + f];
    float sp = fmaxf(x, 0.0f) + log1pf(expf(-fabsf(x)));
    g_effw[f * NB + b] = -sp;
    g_qmw[f * NB + b]  = qmw[b * NF + f];
}

// ---------------------------------------------------------------------------
// K path: warp-level bf16 mma.sync GEMM with 3-term fp32 emulation.
// out[row][bin] = sum_k A[row][k] * W[bin][k] + k_bias[bin]
//   A[:,0:128] = K row, A[:,128:192] = per-pair magnitudes
// ---------------------------------------------------------------------------
constexpr int TILE_M   = 128;
constexpr int KTHREADS = 256;
constexpr int TILES    = 4;

constexpr int OFF_WHI  = 0;
constexpr int OFF_WLO  = OFF_WHI + WBUF_BYTES;     //  51,200
constexpr int OFF_AHI  = OFF_WLO + WBUF_BYTES;     // 102,400
constexpr int OFF_ALO  = OFF_AHI + WBUF_BYTES;     // 153,600
constexpr int OFF_BIAS = OFF_ALO + WBUF_BYTES;     // 204,800
constexpr int SMEMK_SZ = OFF_BIAS + 512;           // 205,312

__global__ void __launch_bounds__(KTHREADS, 1)
kpath_kernel(const float* __restrict__ Kmat,
             const float* __restrict__ kbias,
             float* __restrict__ out)
{
    extern __shared__ char smc[];
    const uint32_t base = smem_u32(smc);
    float* sBias = reinterpret_cast<float*>(smc + OFF_BIAS);

    const int tid  = threadIdx.x;
    const int lane = tid & 31;
    const int wid  = tid >> 5;
    const int wm   = (wid & 1) * 64;    // warp M offset
    const int wn   = (wid >> 1) * 32;   // warp N offset

    // W hi/lo -> smem (layout already final)
    {
        const int4* gh = reinterpret_cast<const int4*>(g_Whi);
        const int4* gl = reinterpret_cast<const int4*>(g_Wlo);
        int4* sh = reinterpret_cast<int4*>(smc + OFF_WHI);
        int4* sl = reinterpret_cast<int4*>(smc + OFF_WLO);
        for (int i = tid; i < WBUF_BYTES / 16; i += KTHREADS) { sh[i] = gh[i]; sl[i] = gl[i]; }
    }
    if (tid < NB) sBias[tid] = kbias[tid];

    // ldmatrix lane addresses (element offsets), constant across k-chunks
    // A x4 groups: g0:(m+l, k0) g1:(m+8+l, k0) g2:(m+l, k0+8) g3:(m+8+l, k0+8)
    const int aRow = wm + (lane & 7) + ((lane >> 3) & 1) * 8;
    const int aK   = ((lane >> 4) & 1) * 8;
    const uint32_t aOff = (uint32_t)(aRow * STRIDE + aK) * 2;
    const uint32_t aHiA = base + OFF_AHI + aOff;
    const uint32_t aLoA = base + OFF_ALO + aOff;
    // B x4 groups: g0:(n+l, k0) g1:(n+l, k0+8) g2:(n+8+l, k0) g3:(n+8+l, k0+8)
    const int bRow = wn + (lane & 7) + ((lane >> 4) & 1) * 8;
    const int bK   = ((lane >> 3) & 1) * 8;
    const uint32_t bOff = (uint32_t)(bRow * STRIDE + bK) * 2;
    const uint32_t bHiA = base + OFF_WHI + bOff;
    const uint32_t bLoA = base + OFF_WLO + bOff;

    constexpr uint32_t MSTEP = 16 * STRIDE * 2;   // 16 rows in bytes

    for (int t = 0; t < TILES; t++) {
        const int rowBase = (blockIdx.x * TILES + t) * TILE_M;
        __syncthreads();   // prior tile's ldmatrix reads done (and W copy on t=0)

        // ---- Fill A tile: LDG f32 -> bf16 hi/lo + magnitudes
        const float4* K4 = reinterpret_cast<const float4*>(Kmat) + (size_t)rowBase * (D / 4);
        #pragma unroll
        for (int it = 0; it < (TILE_M * (D / 4)) / KTHREADS; it++) {
            int i = it * KTHREADS + tid;
            int row = i >> 5, c4 = i & 31;
            float4 v = K4[i];
            __nv_bfloat16 h0, l0, h1, l1, h2, l2, h3, l3;
            bsplit(v.x, h0, l0); bsplit(v.y, h1, l1);
            bsplit(v.z, h2, l2); bsplit(v.w, h3, l3);
            int e0 = row * STRIDE + 4 * c4;
            st_bf2(smc + OFF_AHI, e0, h0, h1);
            st_bf2(smc + OFF_ALO, e0, l0, l1);
            st_bf2(smc + OFF_AHI, e0 + 2, h2, h3);
            st_bf2(smc + OFF_ALO, e0 + 2, l2, l3);
            float m0 = sqrt_approx(fmaf(v.x, v.x, fmaf(v.y, v.y, EPSF)));
            float m1 = sqrt_approx(fmaf(v.z, v.z, fmaf(v.w, v.w, EPSF)));
            __nv_bfloat16 mh0, ml0, mh1, ml1;
            bsplit(m0, mh0, ml0); bsplit(m1, mh1, ml1);
            int em = row * STRIDE + D + 2 * c4;
            st_bf2(smc + OFF_AHI, em, mh0, mh1);
            st_bf2(smc + OFF_ALO, em, ml0, ml1);
        }
        __syncthreads();

        // ---- MMA mainloop: 12 k-chunks x (4m x 4n) frags x 3 terms
        float c[4][4][4];
        #pragma unroll
        for (int i = 0; i < 4; i++)
            #pragma unroll
            for (int j = 0; j < 4; j++)
                #pragma unroll
                for (int r = 0; r < 4; r++) c[i][j][r] = 0.0f;

        #pragma unroll 2
        for (int kc = 0; kc < DT / 16; kc++) {
            const uint32_t kB = (uint32_t)kc * 32;
            uint32_t ah[4][4], al[4][4], bh[2][4], bl[2][4];
            #pragma unroll
            for (int i = 0; i < 4; i++) {
                ldm4(ah[i], aHiA + i * MSTEP + kB);
                ldm4(al[i], aLoA + i * MSTEP + kB);
            }
            #pragma unroll
            for (int jj = 0; jj < 2; jj++) {
                ldm4(bh[jj], bHiA + jj * MSTEP + kB);
                ldm4(bl[jj], bLoA + jj * MSTEP + kB);
            }
            #pragma unroll
            for (int i = 0; i < 4; i++) {
                #pragma unroll
                for (int j = 0; j < 4; j++) {
                    const uint32_t* BH = &bh[j >> 1][(j & 1) * 2];
                    const uint32_t* BL = &bl[j >> 1][(j & 1) * 2];
                    mma16816(c[i][j], ah[i], BH);
                    mma16816(c[i][j], ah[i], BL);
                    mma16816(c[i][j], al[i], BH);
                }
            }
        }

        // ---- Epilogue: bias + direct STG.64 from accumulators
        float2* out2 = reinterpret_cast<float2*>(out);
        const int r0 = rowBase + wm + (lane >> 2);
        #pragma unroll
        for (int j = 0; j < 4; j++) {
            const int col = wn + j * 8 + (lane & 3) * 2;
            const float bx = sBias[col], by = sBias[col + 1];
            const int ch = col >> 1;
            #pragma unroll
            for (int i = 0; i < 4; i++) {
                const int row = r0 + i * 16;
                float2 v0 = make_float2(c[i][j][0] + bx, c[i][j][1] + by);
                float2 v1 = make_float2(c[i][j][2] + bx, c[i][j][3] + by);
                out2[(size_t)row * (NB / 2) + ch] = v0;
                out2[(size_t)(row + 8) * (NB / 2) + ch] = v1;
            }
        }
    }
}

// ---------------------------------------------------------------------------
// Q path (unchanged)
// ---------------------------------------------------------------------------
constexpr int QTHREADS = 256;
constexpr int QPB      = 32;

__global__ void __launch_bounds__(QTHREADS, 1)
qpath_kernel(const float* __restrict__ Q,
             const float* __restrict__ qbias,
             float* __restrict__ outq)
{
    extern __shared__ float smem[];
    float2* sRP  = reinterpret_cast<float2*>(smem);      // NF*NB float2
    float* sEW   = smem + 2 * NF * NB;                   // NF*NB
    float* sMW   = sEW + NF * NB;                        // NF*NB
    float* sQn   = sMW + NF * NB;                        // QPB*D
    float* sQmag = sQn + QPB * D;                        // QPB*NF
    float* sInv  = sQmag + QPB * NF;                     // QPB
    float* sQB   = sInv + QPB;                           // NB

    const int tid = threadIdx.x;
    for (int i = tid; i < NF * NB; i += QTHREADS) {
        sRP[i] = g_rpq[i];
        sEW[i] = g_effw[i];
        sMW[i] = g_qmw[i];
    }
    if (tid < NB) sQB[tid] = qbias[tid];

    const int qbase = blockIdx.x * QPB;
    for (int i = tid; i < QPB * D; i += QTHREADS)
        sQn[i] = Q[(size_t)qbase * D + i];
    __syncthreads();

    {
        int q = tid >> 3, l8 = tid & 7;
        float s = 0.0f;
        #pragma unroll
        for (int j = 0; j < D / 8; j++) {
            float v = sQn[q * D + l8 + 8 * j];
            s = fmaf(v, v, s);
        }
        s += __shfl_down_sync(0xffffffffu, s, 4, 8);
        s += __shfl_down_sync(0xffffffffu, s, 2, 8);
        s += __shfl_down_sync(0xffffffffu, s, 1, 8);
        if (l8 == 0) sInv[q] = 1.0f / (sqrtf(s) + EPSF);
    }
    __syncthreads();
    for (int i = tid; i < QPB * D; i += QTHREADS)
        sQn[i] *= sInv[i >> 7];
    __syncthreads();
    for (int i = tid; i < QPB * NF; i += QTHREADS) {
        int q = i >> 6, f = i & 63;
        float a = sQn[q * D + 2 * f];
        float c = sQn[q * D + 2 * f + 1];
        sQmag[i] = sqrt_approx(fmaf(a, a, fmaf(c, c, EPSF)));
    }
    __syncthreads();

    const int b  = tid & 127;
    const int qg = tid >> 7;
    float acc[16];
    #pragma unroll
    for (int j = 0; j < 16; j++) acc[j] = 0.0f;

    for (int f = 0; f < NF; f++) {
        float2 rp = sRP[f * NB + b];
        float  ew = sEW[f * NB + b];
        float  mw = sMW[f * NB + b];
        #pragma unroll
        for (int j = 0; j < 16; j++) {
            int q = qg * 16 + j;
            float2 qp = *reinterpret_cast<const float2*>(sQn + q * D + 2 * f);
            float d0 = rp.x - qp.x;
            float d1 = rp.y - qp.y;
            float dist = sqrt_approx(fmaf(d0, d0, fmaf(d1, d1, EPSF)));
            acc[j] = fmaf(dist, ew, acc[j]);
            acc[j] = fmaf(sQmag[q * NF + f], mw, acc[j]);
        }
    }

    #pragma unroll
    for (int j = 0; j < 16; j++) {
        int q = qbase + qg * 16 + j;
        outq[(size_t)q * NB + b] = acc[j] + sQB[b];
    }
}

// ---------------------------------------------------------------------------
// Launch
// ---------------------------------------------------------------------------
extern "C" void kernel_launch(void* const* d_in, const int* in_sizes, int n_in,
                              void* d_out, int out_size)
{
    const float* Q      = (const float*)d_in[0];
    const float* Kmat   = (const float*)d_in[1];
    const float* angles = (const float*)d_in[2];
    const float* probes = (const float*)d_in[3];
    const float* kmw    = (const float*)d_in[4];
    const float* kbias  = (const float*)d_in[5];
    const float* qraw   = (const float*)d_in[6];
    const float* qmw    = (const float*)d_in[7];
    const float* qbias  = (const float*)d_in[8];
    float* out = (float*)d_out;

    const size_t smemQ = (size_t)(2 * NF * NB + NF * NB + NF * NB + QPB * D + QPB * NF
                                  + QPB + NB) * sizeof(float);

    cudaFuncSetAttribute(kpath_kernel, cudaFuncAttributeMaxDynamicSharedMemorySize, SMEMK_SZ);
    cudaFuncSetAttribute(qpath_kernel, cudaFuncAttributeMaxDynamicSharedMemorySize, (int)smemQ);

    prep_kernel<<<NB, NF>>>(angles, probes, kmw, qraw, qmw);
    kpath_kernel<<<NK / (TILE_M * TILES), KTHREADS, SMEMK_SZ>>>(Kmat, kbias, out);
    qpath_kernel<<<NQ / QPB, QTHREADS, smemQ>>>(Q, qbias, out + (size_t)NK * NB);
}

// round 6
// speedup vs baseline: 2.4954x; 1.1873x over previous
#include <cuda_runtime.h>
#include <cuda_bf16.h>
#include <cstdint>

// ---------------------------------------------------------------------------
// Problem constants
// ---------------------------------------------------------------------------
#define EPSF 1e-8f

constexpr int NQ = 8192;     // queries
constexpr int NK = 524288;   // keys
constexpr int D  = 128;      // head_dim
constexpr int NF = 64;       // num_freqs
constexpr int NB = 128;      // num_bins
constexpr int DT = 192;      // D + NF  (GEMM K-dimension)

constexpr int STRIDE = 200;              // bf16 elems per row (400B: row%128B==16*i -> conflict-free ldmatrix)
constexpr int WBUF_BYTES = 128 * STRIDE * 2;   // 51,200 B per hi/lo buffer

// ---------------------------------------------------------------------------
// Device scratch (no allocations allowed)
// ---------------------------------------------------------------------------
__device__ __align__(16) __nv_bfloat16 g_Whi[128 * STRIDE];
__device__ __align__(16) __nv_bfloat16 g_Wlo[128 * STRIDE];
__device__ float2 g_rpq[NF * NB];    // rotated probe pairs, [f][b]
__device__ float  g_effw[NF * NB];   // -softplus(q_weights_raw), [f][b]
__device__ float  g_qmw[NF * NB];    // q_magnitude_weights, [f][b]

// ---------------------------------------------------------------------------
// Helpers
// ---------------------------------------------------------------------------
__device__ __forceinline__ float sqrt_approx(float x) {
    float y;
    asm("sqrt.approx.f32 %0, %1;" : "=f"(y) : "f"(x));
    return y;
}

__device__ __forceinline__ void bsplit(float x, __nv_bfloat16& h, __nv_bfloat16& l) {
    h = __float2bfloat16_rn(x);
    l = __float2bfloat16_rn(x - __bfloat162float(h));
}

__device__ __forceinline__ uint32_t packbf(__nv_bfloat16 a, __nv_bfloat16 b) {
    __nv_bfloat162 t = __halves2bfloat162(a, b);
    return *reinterpret_cast<uint32_t*>(&t);
}

__device__ __forceinline__ void st_bf2(char* base, int eidx, __nv_bfloat16 a, __nv_bfloat16 b) {
    *reinterpret_cast<__nv_bfloat162*>(base + 2 * eidx) = __halves2bfloat162(a, b);
}

__device__ __forceinline__ uint32_t smem_u32(const void* p) {
    uint32_t a;
    asm("{ .reg .u64 t; cvta.to.shared.u64 t, %1; cvt.u32.u64 %0, t; }" : "=r"(a) : "l"(p));
    return a;
}

__device__ __forceinline__ void ldm4(uint32_t* r, uint32_t addr) {
    asm volatile("ldmatrix.sync.aligned.m8n8.x4.shared.b16 {%0,%1,%2,%3}, [%4];"
        : "=r"(r[0]), "=r"(r[1]), "=r"(r[2]), "=r"(r[3]) : "r"(addr));
}

__device__ __forceinline__ void mma16816(float* c, const uint32_t* a, const uint32_t* b) {
    asm volatile("mma.sync.aligned.m16n8k16.row.col.f32.bf16.bf16.f32 "
        "{%0,%1,%2,%3}, {%4,%5,%6,%7}, {%8,%9}, {%0,%1,%2,%3};"
        : "+f"(c[0]), "+f"(c[1]), "+f"(c[2]), "+f"(c[3])
        : "r"(a[0]), "r"(a[1]), "r"(a[2]), "r"(a[3]), "r"(b[0]), "r"(b[1]));
}

// ---------------------------------------------------------------------------
// Prep kernel: one block per bin, 64 threads (one per freq)
// ---------------------------------------------------------------------------
__global__ void prep_kernel(const float* __restrict__ angles,
                            const float* __restrict__ probes,
                            const float* __restrict__ kmw,
                            const float* __restrict__ qraw,
                            const float* __restrict__ qmw)
{
    __shared__ float red[2];
    const int b = blockIdx.x;
    const int f = threadIdx.x;   // 0..63

    float p0 = probes[b * D + 2 * f];
    float p1 = probes[b * D + 2 * f + 1];
    float s = fmaf(p0, p0, p1 * p1);
    #pragma unroll
    for (int o = 16; o; o >>= 1) s += __shfl_xor_sync(0xffffffffu, s, o);
    if ((f & 31) == 0) red[f >> 5] = s;
    __syncthreads();
    float inv = 1.0f / (sqrtf(red[0] + red[1]) + EPSF);
    p0 *= inv; p1 *= inv;

    float a  = angles[f];
    float ca = cosf(a), sa = sinf(a);
    float r0 = p0 * ca - p1 * sa;
    float r1 = p0 * sa + p1 * ca;
    g_rpq[f * NB + b] = make_float2(r0, r1);

    __nv_bfloat16 h0, l0, h1, l1;
    bsplit(r0, h0, l0); bsplit(r1, h1, l1);
    int e = b * STRIDE + 2 * f;
    st_bf2((char*)g_Whi, e, h0, h1);
    st_bf2((char*)g_Wlo, e, l0, l1);

    float w = kmw[b * NF + f];
    __nv_bfloat16 wh, wl;
    bsplit(w, wh, wl);
    int em = b * STRIDE + D + f;
    g_Whi[em] = wh;
    g_Wlo[em] = wl;

    if (f < 8) { g_Whi[b * STRIDE + 192 + f] = __float2bfloat16(0.f); g_Wlo[b * STRIDE + 192 + f] = __float2bfloat16(0.f); }

    float x  = qraw[b * NF + f];
    float sp = fmaxf(x, 0.0f) + log1pf(expf(-fabsf(x)));
    g_effw[f * NB + b] = -sp;
    g_qmw[f * NB + b]  = qmw[b * NF + f];
}

// ---------------------------------------------------------------------------
// K path: warp-level bf16 mma.sync GEMM, 3-term fp32 emulation.
// 512 threads, 16 warps in 4(M)x4(N) grid, 32x32 output per warp.
// Register prefetch of next tile's raw K hidden under current MMA loop.
// ---------------------------------------------------------------------------
constexpr int TILE_M   = 128;
constexpr int KTHREADS = 512;
constexpr int TILES    = 4;
constexpr int FPT      = (TILE_M * (D / 4)) / KTHREADS;   // float4 per thread = 8

constexpr int OFF_WHI  = 0;
constexpr int OFF_WLO  = OFF_WHI + WBUF_BYTES;     //  51,200
constexpr int OFF_AHI  = OFF_WLO + WBUF_BYTES;     // 102,400
constexpr int OFF_ALO  = OFF_AHI + WBUF_BYTES;     // 153,600
constexpr int OFF_BIAS = OFF_ALO + WBUF_BYTES;     // 204,800
constexpr int SMEMK_SZ = OFF_BIAS + 512;           // 205,312

__global__ void __launch_bounds__(KTHREADS, 1)
kpath_kernel(const float* __restrict__ Kmat,
             const float* __restrict__ kbias,
             float* __restrict__ out)
{
    extern __shared__ char smc[];
    const uint32_t base = smem_u32(smc);
    float* sBias = reinterpret_cast<float*>(smc + OFF_BIAS);

    const int tid  = threadIdx.x;
    const int lane = tid & 31;
    const int wid  = tid >> 5;
    const int wm   = (wid & 3) * 32;    // warp M offset (4 groups)
    const int wn   = (wid >> 2) * 32;   // warp N offset (4 groups)

    // W hi/lo -> smem (layout already final)
    {
        const int4* gh = reinterpret_cast<const int4*>(g_Whi);
        const int4* gl = reinterpret_cast<const int4*>(g_Wlo);
        int4* sh = reinterpret_cast<int4*>(smc + OFF_WHI);
        int4* sl = reinterpret_cast<int4*>(smc + OFF_WLO);
        for (int i = tid; i < WBUF_BYTES / 16; i += KTHREADS) { sh[i] = gh[i]; sl[i] = gl[i]; }
    }
    if (tid < NB) sBias[tid] = kbias[tid];

    // ldmatrix lane addresses (constant across chunks; chunk offset added as immediate)
    // A frag i (i=0,1): rows wm + i*16 + pattern
    const int aRow = wm + (lane & 7) + ((lane >> 3) & 1) * 8;
    const int aK   = ((lane >> 4) & 1) * 8;
    const uint32_t aOff = (uint32_t)(aRow * STRIDE + aK) * 2;
    const uint32_t aHiA = base + OFF_AHI + aOff;
    const uint32_t aLoA = base + OFF_ALO + aOff;
    // B frag group jj (jj=0,1): bins wn + jj*16 + pattern
    const int bRow = wn + (lane & 7) + ((lane >> 4) & 1) * 8;
    const int bK   = ((lane >> 3) & 1) * 8;
    const uint32_t bOff = (uint32_t)(bRow * STRIDE + bK) * 2;
    const uint32_t bHiA = base + OFF_WHI + bOff;
    const uint32_t bLoA = base + OFF_WLO + bOff;

    constexpr uint32_t MSTEP = 16 * STRIDE * 2;   // 16 rows in bytes

    // Prologue: prefetch raw tile 0 into registers
    float4 pf[FPT];
    {
        const float4* K4 = reinterpret_cast<const float4*>(Kmat)
                         + (size_t)(blockIdx.x * TILES) * TILE_M * (D / 4);
        #pragma unroll
        for (int it = 0; it < FPT; it++) pf[it] = K4[it * KTHREADS + tid];
    }
    __syncthreads();   // W + bias ready

    for (int t = 0; t < TILES; t++) {
        const int rowBase = (blockIdx.x * TILES + t) * TILE_M;

        // ---- Convert prefetched registers -> A hi/lo smem
        #pragma unroll
        for (int it = 0; it < FPT; it++) {
            const int i = it * KTHREADS + tid;
            const int row = i >> 5, c4 = i & 31;
            float4 v = pf[it];
            __nv_bfloat16 h0, l0, h1, l1, h2, l2, h3, l3;
            bsplit(v.x, h0, l0); bsplit(v.y, h1, l1);
            bsplit(v.z, h2, l2); bsplit(v.w, h3, l3);
            const int e0 = row * STRIDE + 4 * c4;           // 8B-aligned element idx
            uint2 hv = make_uint2(packbf(h0, h1), packbf(h2, h3));
            uint2 lv = make_uint2(packbf(l0, l1), packbf(l2, l3));
            *reinterpret_cast<uint2*>(smc + OFF_AHI + 2 * e0) = hv;
            *reinterpret_cast<uint2*>(smc + OFF_ALO + 2 * e0) = lv;
            float m0 = sqrt_approx(fmaf(v.x, v.x, fmaf(v.y, v.y, EPSF)));
            float m1 = sqrt_approx(fmaf(v.z, v.z, fmaf(v.w, v.w, EPSF)));
            __nv_bfloat16 mh0, ml0, mh1, ml1;
            bsplit(m0, mh0, ml0); bsplit(m1, mh1, ml1);
            const int em = row * STRIDE + D + 2 * c4;
            st_bf2(smc + OFF_AHI, em, mh0, mh1);
            st_bf2(smc + OFF_ALO, em, ml0, ml1);
        }
        __syncthreads();   // A ready

        // ---- Prefetch next tile's raw data (completes under the MMA loop)
        if (t + 1 < TILES) {
            const float4* K4n = reinterpret_cast<const float4*>(Kmat)
                              + (size_t)(rowBase + TILE_M) * (D / 4);
            #pragma unroll
            for (int it = 0; it < FPT; it++) pf[it] = K4n[it * KTHREADS + tid];
        }

        // ---- MMA mainloop: 12 k-chunks, (2m x 4n8) frags x 3 terms
        float c[2][4][4];
        #pragma unroll
        for (int i = 0; i < 2; i++)
            #pragma unroll
            for (int j = 0; j < 4; j++)
                #pragma unroll
                for (int r = 0; r < 4; r++) c[i][j][r] = 0.0f;

        #pragma unroll
        for (int kc = 0; kc < DT / 16; kc++) {
            const uint32_t kB = (uint32_t)kc * 32;
            uint32_t ah[2][4], al[2][4], bh[2][4], bl[2][4];
            #pragma unroll
            for (int i = 0; i < 2; i++) {
                ldm4(ah[i], aHiA + i * MSTEP + kB);
                ldm4(al[i], aLoA + i * MSTEP + kB);
            }
            #pragma unroll
            for (int jj = 0; jj < 2; jj++) {
                ldm4(bh[jj], bHiA + jj * MSTEP + kB);
                ldm4(bl[jj], bLoA + jj * MSTEP + kB);
            }
            #pragma unroll
            for (int i = 0; i < 2; i++) {
                #pragma unroll
                for (int j = 0; j < 4; j++) {
                    const uint32_t* BH = &bh[j >> 1][(j & 1) * 2];
                    const uint32_t* BL = &bl[j >> 1][(j & 1) * 2];
                    mma16816(c[i][j], ah[i], BH);
                    mma16816(c[i][j], ah[i], BL);
                    mma16816(c[i][j], al[i], BH);
                }
            }
        }

        // ---- Epilogue: bias + direct STG.64 from accumulators
        float2* out2 = reinterpret_cast<float2*>(out);
        const int r0 = rowBase + wm + (lane >> 2);
        #pragma unroll
        for (int j = 0; j < 4; j++) {
            const int col = wn + j * 8 + (lane & 3) * 2;
            const float bx = sBias[col], by = sBias[col + 1];
            const int ch = col >> 1;
            #pragma unroll
            for (int i = 0; i < 2; i++) {
                const int row = r0 + i * 16;
                float2 v0 = make_float2(c[i][j][0] + bx, c[i][j][1] + by);
                float2 v1 = make_float2(c[i][j][2] + bx, c[i][j][3] + by);
                out2[(size_t)row * (NB / 2) + ch] = v0;
                out2[(size_t)(row + 8) * (NB / 2) + ch] = v1;
            }
        }
        __syncthreads();   // all warps done reading A before next convert
    }
}

// ---------------------------------------------------------------------------
// Q path (unchanged)
// ---------------------------------------------------------------------------
constexpr int QTHREADS = 256;
constexpr int QPB      = 32;

__global__ void __launch_bounds__(QTHREADS, 1)
qpath_kernel(const float* __restrict__ Q,
             const float* __restrict__ qbias,
             float* __restrict__ outq)
{
    extern __shared__ float smem[];
    float2* sRP  = reinterpret_cast<float2*>(smem);      // NF*NB float2
    float* sEW   = smem + 2 * NF * NB;                   // NF*NB
    float* sMW   = sEW + NF * NB;                        // NF*NB
    float* sQn   = sMW + NF * NB;                        // QPB*D
    float* sQmag = sQn + QPB * D;                        // QPB*NF
    float* sInv  = sQmag + QPB * NF;                     // QPB
    float* sQB   = sInv + QPB;                           // NB

    const int tid = threadIdx.x;
    for (int i = tid; i < NF * NB; i += QTHREADS) {
        sRP[i] = g_rpq[i];
        sEW[i] = g_effw[i];
        sMW[i] = g_qmw[i];
    }
    if (tid < NB) sQB[tid] = qbias[tid];

    const int qbase = blockIdx.x * QPB;
    for (int i = tid; i < QPB * D; i += QTHREADS)
        sQn[i] = Q[(size_t)qbase * D + i];
    __syncthreads();

    {
        int q = tid >> 3, l8 = tid & 7;
        float s = 0.0f;
        #pragma unroll
        for (int j = 0; j < D / 8; j++) {
            float v = sQn[q * D + l8 + 8 * j];
            s = fmaf(v, v, s);
        }
        s += __shfl_down_sync(0xffffffffu, s, 4, 8);
        s += __shfl_down_sync(0xffffffffu, s, 2, 8);
        s += __shfl_down_sync(0xffffffffu, s, 1, 8);
        if (l8 == 0) sInv[q] = 1.0f / (sqrtf(s) + EPSF);
    }
    __syncthreads();
    for (int i = tid; i < QPB * D; i += QTHREADS)
        sQn[i] *= sInv[i >> 7];
    __syncthreads();
    for (int i = tid; i < QPB * NF; i += QTHREADS) {
        int q = i >> 6, f = i & 63;
        float a = sQn[q * D + 2 * f];
        float c = sQn[q * D + 2 * f + 1];
        sQmag[i] = sqrt_approx(fmaf(a, a, fmaf(c, c, EPSF)));
    }
    __syncthreads();

    const int b  = tid & 127;
    const int qg = tid >> 7;
    float acc[16];
    #pragma unroll
    for (int j = 0; j < 16; j++) acc[j] = 0.0f;

    for (int f = 0; f < NF; f++) {
        float2 rp = sRP[f * NB + b];
        float  ew = sEW[f * NB + b];
        float  mw = sMW[f * NB + b];
        #pragma unroll
        for (int j = 0; j < 16; j++) {
            int q = qg * 16 + j;
            float2 qp = *reinterpret_cast<const float2*>(sQn + q * D + 2 * f);
            float d0 = rp.x - qp.x;
            float d1 = rp.y - qp.y;
            float dist = sqrt_approx(fmaf(d0, d0, fmaf(d1, d1, EPSF)));
            acc[j] = fmaf(dist, ew, acc[j]);
            acc[j] = fmaf(sQmag[q * NF + f], mw, acc[j]);
        }
    }

    #pragma unroll
    for (int j = 0; j < 16; j++) {
        int q = qbase + qg * 16 + j;
        outq[(size_t)q * NB + b] = acc[j] + sQB[b];
    }
}

// ---------------------------------------------------------------------------
// Launch
// ---------------------------------------------------------------------------
extern "C" void kernel_launch(void* const* d_in, const int* in_sizes, int n_in,
                              void* d_out, int out_size)
{
    const float* Q      = (const float*)d_in[0];
    const float* Kmat   = (const float*)d_in[1];
    const float* angles = (const float*)d_in[2];
    const float* probes = (const float*)d_in[3];
    const float* kmw    = (const float*)d_in[4];
    const float* kbias  = (const float*)d_in[5];
    const float* qraw   = (const float*)d_in[6];
    const float* qmw    = (const float*)d_in[7];
    const float* qbias  = (const float*)d_in[8];
    float* out = (float*)d_out;

    const size_t smemQ = (size_t)(2 * NF * NB + NF * NB + NF * NB + QPB * D + QPB * NF
                                  + QPB + NB) * sizeof(float);

    cudaFuncSetAttribute(kpath_kernel, cudaFuncAttributeMaxDynamicSharedMemorySize, SMEMK_SZ);
    cudaFuncSetAttribute(qpath_kernel, cudaFuncAttributeMaxDynamicSharedMemorySize, (int)smemQ);

    prep_kernel<<<NB, NF>>>(angles, probes, kmw, qraw, qmw);
    kpath_kernel<<<NK / (TILE_M * TILES), KTHREADS, SMEMK_SZ>>>(Kmat, kbias, out);
    qpath_kernel<<<NQ / QPB, QTHREADS, smemQ>>>(Q, qbias, out + (size_t)NK * NB);
}